// round 1
// baseline (speedup 1.0000x reference)
#include <cuda_runtime.h>

#define IC1 10
#define OC1 64
#define OC2 128
#define NB  64          // 2 images x 32 batch
#define TY  8           // pooled rows per block
#define TX  16          // pooled cols per block
// input tile region: (2*TY+2)=18 rows x (2*TX+2)=34 cols per input channel

__device__ int   g_cnt[NB][OC1][9];    // S, Rfirst, Rlast, Cfirst, Clast, q_tl, q_tr, q_bl, q_br
__device__ float g_s2[NB][OC2];
__device__ float g_inv1[OC1],  g_beta1[OC1];
__device__ float g_inv2[OC2],  g_beta2[OC2];

// ---------------------------------------------------------------------------
// prep: zero counters, fold BN params into (inv, beta)
// ---------------------------------------------------------------------------
__global__ void prep_kernel(const float* __restrict__ g1, const float* __restrict__ b1,
                            const float* __restrict__ m1, const float* __restrict__ v1,
                            const float* __restrict__ g2, const float* __restrict__ b2,
                            const float* __restrict__ m2, const float* __restrict__ v2) {
    int t = blockIdx.x * blockDim.x + threadIdx.x;
    int* c = &g_cnt[0][0][0];
    for (int i = t; i < NB * OC1 * 9; i += gridDim.x * blockDim.x) c[i] = 0;
    if (blockIdx.x == 0) {
        if (t < OC1) {
            float inv = g1[t] / sqrtf(v1[t] + 1e-5f);
            g_inv1[t] = inv;
            g_beta1[t] = b1[t] - m1[t] * inv;
        }
        if (t < OC2) {
            float inv = g2[t] / sqrtf(v2[t] + 1e-5f);
            g_inv2[t] = inv;
            g_beta2[t] = b2[t] - m2[t] * inv;
        }
    }
}

// ---------------------------------------------------------------------------
// stage A: conv1 + BN + maxpool2 + spike + 9-aggregate reduction
// grid (8, 16, 64), block 128
// ---------------------------------------------------------------------------
__global__ __launch_bounds__(128) void stageA_kernel(const float* __restrict__ x0,
                                                     const float* __restrict__ x1,
                                                     const float* __restrict__ w1) {
    __shared__ __align__(16) float s_in[IC1 * 18 * 34];   // 24480 B
    __shared__ __align__(16) float s_w[90 * 64];          // [ic*9+k][o], 23040 B
    __shared__ int sc[5][OC1];                            // 1280 B  (total 48800 <= 49152)

    const int tid = threadIdx.x;
    const int bx = blockIdx.x, by = blockIdx.y, n = blockIdx.z;
    const float* __restrict__ x = (n < 32) ? x0 : x1;
    const int b = n & 31;

    // weights transposed: s_w[r*64+o] = w1[o*90+r]
    for (int i = tid; i < 90 * 64; i += 128) {
        int r = i >> 6, o = i & 63;
        s_w[i] = __ldg(&w1[o * 90 + r]);
    }
    for (int i = tid; i < 5 * OC1; i += 128) ((int*)sc)[i] = 0;

    // input tile with SAME zero padding
    const int iy0 = by * (2 * TY) - 1;
    const int ix0 = bx * (2 * TX) - 1;
    for (int i = tid; i < IC1 * 18 * 34; i += 128) {
        int ic = i / 612, r2 = i % 612;
        int rw = r2 / 34, cl = r2 % 34;
        int gy = iy0 + rw, gx = ix0 + cl;
        float v = 0.f;
        if ((unsigned)gy < 256u && (unsigned)gx < 256u)
            v = __ldg(&x[((b * IC1 + ic) * 256 + gy) * 256 + gx]);
        s_in[i] = v;
    }
    __syncthreads();

    const int lpx = tid & 15, lpy = tid >> 4;
    const int gpy = by * TY + lpy, gpx = bx * TX + lpx;
    const int lane = tid & 31;
    const bool edge = (by == 0) | (by == 15) | (bx == 0) | (bx == 7);
    const int rr = 2 * lpy, cc = 2 * lpx;

    for (int g = 0; g < 8; ++g) {
        float a[8][4];
#pragma unroll
        for (int o = 0; o < 8; ++o) { a[o][0] = a[o][1] = a[o][2] = a[o][3] = 0.f; }

        for (int ic = 0; ic < IC1; ++ic) {
            float r[4][4];
#pragma unroll
            for (int i = 0; i < 4; ++i) {
                const float2* p = reinterpret_cast<const float2*>(&s_in[ic * 612 + (rr + i) * 34 + cc]);
                float2 u = p[0], w = p[1];
                r[i][0] = u.x; r[i][1] = u.y; r[i][2] = w.x; r[i][3] = w.y;
            }
            const float* wp = &s_w[ic * 9 * 64 + g * 8];
#pragma unroll
            for (int k = 0; k < 9; ++k) {
                const int ky = k / 3, kx = k % 3;
                float4 wa = *reinterpret_cast<const float4*>(&wp[k * 64]);
                float4 wb = *reinterpret_cast<const float4*>(&wp[k * 64 + 4]);
                float ws[8] = {wa.x, wa.y, wa.z, wa.w, wb.x, wb.y, wb.z, wb.w};
#pragma unroll
                for (int o = 0; o < 8; ++o) {
                    float w = ws[o];
                    a[o][0] = fmaf(w, r[ky][kx],         a[o][0]);
                    a[o][1] = fmaf(w, r[ky][kx + 1],     a[o][1]);
                    a[o][2] = fmaf(w, r[ky + 1][kx],     a[o][2]);
                    a[o][3] = fmaf(w, r[ky + 1][kx + 1], a[o][3]);
                }
            }
        }
        // BN + maxpool + spike + reduce
#pragma unroll
        for (int o = 0; o < 8; ++o) {
            int oc = g * 8 + o;
            float inv = __ldg(&g_inv1[oc]);
            float bet = __ldg(&g_beta1[oc]);
            float mx = fmaxf(fmaxf(a[o][0], a[o][1]), fmaxf(a[o][2], a[o][3]));
            float mn = fminf(fminf(a[o][0], a[o][1]), fminf(a[o][2], a[o][3]));
            float z = (inv >= 0.f ? mx : mn) * inv + bet;
            bool sp = z > 1.0f;
            unsigned bal = __ballot_sync(0xffffffffu, sp);
            if (lane == 0 && bal) atomicAdd(&sc[0][oc], __popc(bal));
            if (edge) {
                unsigned bR0 = __ballot_sync(0xffffffffu, sp && (gpy == 0));
                unsigned bR1 = __ballot_sync(0xffffffffu, sp && (gpy == 127));
                unsigned bC0 = __ballot_sync(0xffffffffu, sp && (gpx == 0));
                unsigned bC1 = __ballot_sync(0xffffffffu, sp && (gpx == 127));
                if (lane == 0) {
                    if (bR0) atomicAdd(&sc[1][oc], __popc(bR0));
                    if (bR1) atomicAdd(&sc[2][oc], __popc(bR1));
                    if (bC0) atomicAdd(&sc[3][oc], __popc(bC0));
                    if (bC1) atomicAdd(&sc[4][oc], __popc(bC1));
                }
                if (sp) {  // corner bits (unique writer per corner; buffer pre-zeroed)
                    if (gpy == 0   && gpx == 0)   g_cnt[n][oc][5] = 1;
                    else if (gpy == 0   && gpx == 127) g_cnt[n][oc][6] = 1;
                    else if (gpy == 127 && gpx == 0)   g_cnt[n][oc][7] = 1;
                    else if (gpy == 127 && gpx == 127) g_cnt[n][oc][8] = 1;
                }
            }
        }
    }
    __syncthreads();
    if (tid < OC1) {
#pragma unroll
        for (int j = 0; j < 5; ++j) {
            int v = sc[j][tid];
            if (v) atomicAdd(&g_cnt[n][tid][j], v);
        }
    }
}

// ---------------------------------------------------------------------------
// stage B: analytic conv2-mean via T aggregates, BN2, spike -> g_s2
// grid 64 (one per n), block 128 (one per output channel)
// ---------------------------------------------------------------------------
__global__ __launch_bounds__(128) void stageB_kernel(const float* __restrict__ w2) {
    __shared__ __align__(16) float sT[OC1 * 9];
    const int n = blockIdx.x, tid = threadIdx.x;
    if (tid < OC1) {
        const int* c = g_cnt[n][tid];
        int S = c[0], Rf = c[1], Rl = c[2], Cf = c[3], Cl = c[4];
        int Re[3] = {Rl, 0, Rf};           // ky=0 excludes last row; ky=2 excludes first
        int Ce[3] = {Cl, 0, Cf};
        int Q[9]  = {c[8], 0, c[7],  0, 0, 0,  c[6], 0, c[5]};  // double-excluded corners
#pragma unroll
        for (int k = 0; k < 9; ++k)
            sT[tid * 9 + k] = (float)(S - Re[k / 3] - Ce[k % 3] + Q[k]);
    }
    __syncthreads();
    const int o = tid;
    const float4* w4 = reinterpret_cast<const float4*>(w2 + o * 576);
    float acc = 0.f;
#pragma unroll 8
    for (int i = 0; i < 144; ++i) {
        float4 wv = __ldg(&w4[i]);
        acc = fmaf(wv.x, sT[4 * i],     acc);
        acc = fmaf(wv.y, sT[4 * i + 1], acc);
        acc = fmaf(wv.z, sT[4 * i + 2], acc);
        acc = fmaf(wv.w, sT[4 * i + 3], acc);
    }
    float z = acc * (1.f / 16384.f);
    z = z * g_inv2[o] + g_beta2[o];
    g_s2[n][o] = (z > 1.f) ? 1.f : 0.f;
}

// ---------------------------------------------------------------------------
// stage C: feat = |s0 - s1|, fc1+relu, fc2  -> out (32,5)
// ---------------------------------------------------------------------------
__global__ __launch_bounds__(256) void stageC_kernel(const float* __restrict__ fc1w,
                                                     const float* __restrict__ fc1b,
                                                     const float* __restrict__ fc2w,
                                                     const float* __restrict__ fc2b,
                                                     float* __restrict__ out) {
    __shared__ float f[32][128];
    __shared__ float h[32][64];
    const int tid = threadIdx.x;
    for (int i = tid; i < 32 * 128; i += 256) {
        int n = i >> 7, j = i & 127;
        f[n][j] = fabsf(g_s2[n][j] - g_s2[n + 32][j]);
    }
    __syncthreads();
    for (int i = tid; i < 32 * 64; i += 256) {
        int n = i >> 6, k = i & 63;
        float acc = fc1b[k];
        const float* wr = fc1w + k * 128;
#pragma unroll 4
        for (int j = 0; j < 128; ++j) acc = fmaf(f[n][j], wr[j], acc);
        h[n][k] = fmaxf(acc, 0.f);
    }
    __syncthreads();
    if (tid < 160) {
        int n = tid / 5, c = tid % 5;
        float acc = fc2b[c];
        const float* wr = fc2w + c * 64;
#pragma unroll
        for (int k = 0; k < 64; ++k) acc = fmaf(h[n][k], wr[k], acc);
        out[n * 5 + c] = acc;
    }
}

extern "C" void kernel_launch(void* const* d_in, const int* in_sizes, int n_in,
                              void* d_out, int out_size) {
    const float* x0   = (const float*)d_in[0];
    const float* x1   = (const float*)d_in[1];
    const float* w1   = (const float*)d_in[2];
    const float* b1g  = (const float*)d_in[3];
    const float* b1b  = (const float*)d_in[4];
    const float* b1m  = (const float*)d_in[5];
    const float* b1v  = (const float*)d_in[6];
    const float* w2   = (const float*)d_in[7];
    const float* b2g  = (const float*)d_in[8];
    const float* b2b  = (const float*)d_in[9];
    const float* b2m  = (const float*)d_in[10];
    const float* b2v  = (const float*)d_in[11];
    const float* fc1w = (const float*)d_in[12];
    const float* fc1b = (const float*)d_in[13];
    const float* fc2w = (const float*)d_in[14];
    const float* fc2b = (const float*)d_in[15];

    prep_kernel<<<32, 256>>>(b1g, b1b, b1m, b1v, b2g, b2b, b2m, b2v);
    dim3 gridA(8, 16, 64);
    stageA_kernel<<<gridA, 128>>>(x0, x1, w1);
    stageB_kernel<<<64, 128>>>(w2);
    stageC_kernel<<<1, 256>>>(fc1w, fc1b, fc2w, fc2b, (float*)d_out);
}

// round 2
// speedup vs baseline: 1.2854x; 1.2854x over previous
#include <cuda_runtime.h>

#define IC1 10
#define OC1 64
#define OC2 128
#define NB  64          // 2 images x 32 batch
#define TY  8           // pooled rows per block
#define TX  16          // pooled cols per block

__device__ int   g_cnt[NB][OC1][9];    // S, Rfirst, Rlast, Cfirst, Clast, q_tl, q_tr, q_bl, q_br
__device__ float g_s2[NB][OC2];
__device__ float g_inv1[OC1],  g_beta1[OC1];
__device__ float g_inv2[OC2],  g_beta2[OC2];

// packed fp32x2 helpers (sm_103a FFMA2 path — PTX only, ptxas won't auto-fuse)
#define FMA_X2(d, a, b, c) \
    asm("fma.rn.f32x2 %0, %1, %2, %3;" : "=l"(d) : "l"(a), "l"(b), "l"(c))
#define PACK_DUP(d, v) \
    asm("mov.b64 %0, {%1, %1};" : "=l"(d) : "r"(__float_as_uint(v)))
#define UNPACK_X2(lo, hi, v) \
    asm("mov.b64 {%0, %1}, %2;" : "=r"(lo), "=r"(hi) : "l"(v))

// ---------------------------------------------------------------------------
// prep: zero counters, fold BN params into (inv, beta)
// ---------------------------------------------------------------------------
__global__ void prep_kernel(const float* __restrict__ g1, const float* __restrict__ b1,
                            const float* __restrict__ m1, const float* __restrict__ v1,
                            const float* __restrict__ g2, const float* __restrict__ b2,
                            const float* __restrict__ m2, const float* __restrict__ v2) {
    int t = blockIdx.x * blockDim.x + threadIdx.x;
    int* c = &g_cnt[0][0][0];
    for (int i = t; i < NB * OC1 * 9; i += gridDim.x * blockDim.x) c[i] = 0;
    if (blockIdx.x == 0) {
        if (t < OC1) {
            float inv = g1[t] / sqrtf(v1[t] + 1e-5f);
            g_inv1[t] = inv;
            g_beta1[t] = b1[t] - m1[t] * inv;
        }
        if (t < OC2) {
            float inv = g2[t] / sqrtf(v2[t] + 1e-5f);
            g_inv2[t] = inv;
            g_beta2[t] = b2[t] - m2[t] * inv;
        }
    }
}

// ---------------------------------------------------------------------------
// stage A: conv1 + BN + maxpool2 + spike + 9-aggregate reduction (FFMA2 core)
// grid (8, 16, 64), block 128
// ---------------------------------------------------------------------------
__global__ __launch_bounds__(128, 4) void stageA_kernel(const float* __restrict__ x0,
                                                        const float* __restrict__ x1,
                                                        const float* __restrict__ w1) {
    __shared__ __align__(16) float s_in[IC1 * 18 * 34];   // 24480 B
    __shared__ __align__(16) float s_w[90 * 64];          // [ic*9+k][o], 23040 B
    __shared__ int sc[5][OC1];                            // 1280 B  (total 48800 <= 49152)

    const int tid = threadIdx.x;
    const int bx = blockIdx.x, by = blockIdx.y, n = blockIdx.z;
    const float* __restrict__ x = (n < 32) ? x0 : x1;
    const int b = n & 31;

    // weights transposed: s_w[r*64+o] = w1[o*90+r]
    for (int i = tid; i < 90 * 64; i += 128) {
        int r = i >> 6, o = i & 63;
        s_w[i] = __ldg(&w1[o * 90 + r]);
    }
    for (int i = tid; i < 5 * OC1; i += 128) ((int*)sc)[i] = 0;

    // input tile with SAME zero padding
    const int iy0 = by * (2 * TY) - 1;
    const int ix0 = bx * (2 * TX) - 1;
    for (int i = tid; i < IC1 * 18 * 34; i += 128) {
        int ic = i / 612, r2 = i % 612;
        int rw = r2 / 34, cl = r2 % 34;
        int gy = iy0 + rw, gx = ix0 + cl;
        float v = 0.f;
        if ((unsigned)gy < 256u && (unsigned)gx < 256u)
            v = __ldg(&x[((b * IC1 + ic) * 256 + gy) * 256 + gx]);
        s_in[i] = v;
    }
    __syncthreads();

    const int lpx = tid & 15, lpy = tid >> 4;
    const int gpy = by * TY + lpy, gpx = bx * TX + lpx;
    const int lane = tid & 31;
    const bool edge = (by == 0) | (by == 15) | (bx == 0) | (bx == 7);
    const int rr = 2 * lpy, cc = 2 * lpx;

    for (int g = 0; g < 8; ++g) {
        // acc[op][pos]: packed pair over (oc = g*8 + 2*op, +1); pos = 2x2 pool window
        unsigned long long acc[4][4];
#pragma unroll
        for (int op = 0; op < 4; ++op)
#pragma unroll
            for (int p = 0; p < 4; ++p) acc[op][p] = 0ULL;

        for (int ic = 0; ic < IC1; ++ic) {
            float rv[4][4];
#pragma unroll
            for (int i = 0; i < 4; ++i) {
                const float2* p = reinterpret_cast<const float2*>(&s_in[ic * 612 + (rr + i) * 34 + cc]);
                float2 u = p[0], w = p[1];
                rv[i][0] = u.x; rv[i][1] = u.y; rv[i][2] = w.x; rv[i][3] = w.y;
            }
            unsigned long long rd[4][4];
#pragma unroll
            for (int i = 0; i < 4; ++i)
#pragma unroll
                for (int j = 0; j < 4; ++j) PACK_DUP(rd[i][j], rv[i][j]);

            const ulonglong2* wp = reinterpret_cast<const ulonglong2*>(&s_w[ic * 576 + g * 8]);
#pragma unroll
            for (int k = 0; k < 9; ++k) {
                const int ky = k / 3, kx = k % 3;
                ulonglong2 wab = wp[k * 16];        // pairs (o0,o1),(o2,o3)
                ulonglong2 wcd = wp[k * 16 + 1];    // pairs (o4,o5),(o6,o7)
                unsigned long long wq[4] = {wab.x, wab.y, wcd.x, wcd.y};
#pragma unroll
                for (int op = 0; op < 4; ++op) {
                    FMA_X2(acc[op][0], wq[op], rd[ky][kx],         acc[op][0]);
                    FMA_X2(acc[op][1], wq[op], rd[ky][kx + 1],     acc[op][1]);
                    FMA_X2(acc[op][2], wq[op], rd[ky + 1][kx],     acc[op][2]);
                    FMA_X2(acc[op][3], wq[op], rd[ky + 1][kx + 1], acc[op][3]);
                }
            }
        }
        // BN + maxpool + spike + reduce
#pragma unroll
        for (int op = 0; op < 4; ++op) {
            float v[2][4];
#pragma unroll
            for (int p = 0; p < 4; ++p) {
                unsigned lo, hi;
                UNPACK_X2(lo, hi, acc[op][p]);
                v[0][p] = __uint_as_float(lo);
                v[1][p] = __uint_as_float(hi);
            }
#pragma unroll
            for (int s = 0; s < 2; ++s) {
                int oc = g * 8 + op * 2 + s;
                float inv = __ldg(&g_inv1[oc]);
                float bet = __ldg(&g_beta1[oc]);
                float mx = fmaxf(fmaxf(v[s][0], v[s][1]), fmaxf(v[s][2], v[s][3]));
                float mn = fminf(fminf(v[s][0], v[s][1]), fminf(v[s][2], v[s][3]));
                float z = (inv >= 0.f ? mx : mn) * inv + bet;
                bool sp = z > 1.0f;
                unsigned bal = __ballot_sync(0xffffffffu, sp);
                if (lane == 0 && bal) atomicAdd(&sc[0][oc], __popc(bal));
                if (edge) {
                    unsigned bR0 = __ballot_sync(0xffffffffu, sp && (gpy == 0));
                    unsigned bR1 = __ballot_sync(0xffffffffu, sp && (gpy == 127));
                    unsigned bC0 = __ballot_sync(0xffffffffu, sp && (gpx == 0));
                    unsigned bC1 = __ballot_sync(0xffffffffu, sp && (gpx == 127));
                    if (lane == 0) {
                        if (bR0) atomicAdd(&sc[1][oc], __popc(bR0));
                        if (bR1) atomicAdd(&sc[2][oc], __popc(bR1));
                        if (bC0) atomicAdd(&sc[3][oc], __popc(bC0));
                        if (bC1) atomicAdd(&sc[4][oc], __popc(bC1));
                    }
                    if (sp) {  // corner bits (unique writer per corner; buffer pre-zeroed)
                        if (gpy == 0   && gpx == 0)   g_cnt[n][oc][5] = 1;
                        else if (gpy == 0   && gpx == 127) g_cnt[n][oc][6] = 1;
                        else if (gpy == 127 && gpx == 0)   g_cnt[n][oc][7] = 1;
                        else if (gpy == 127 && gpx == 127) g_cnt[n][oc][8] = 1;
                    }
                }
            }
        }
    }
    __syncthreads();
    if (tid < OC1) {
#pragma unroll
        for (int j = 0; j < 5; ++j) {
            int v = sc[j][tid];
            if (v) atomicAdd(&g_cnt[n][tid][j], v);
        }
    }
}

// ---------------------------------------------------------------------------
// stage B: analytic conv2-mean via T aggregates, BN2, spike -> g_s2
// grid 64 (n), block 256 (8 warps x 16 oc, coalesced w2 reads + shfl reduce)
// ---------------------------------------------------------------------------
__global__ __launch_bounds__(256) void stageB_kernel(const float* __restrict__ w2) {
    __shared__ __align__(16) float sT[OC1 * 9];
    const int n = blockIdx.x, tid = threadIdx.x;
    const int lane = tid & 31, warp = tid >> 5;
    if (tid < OC1) {
        const int* c = g_cnt[n][tid];
        int S = c[0], Rf = c[1], Rl = c[2], Cf = c[3], Cl = c[4];
        int Re[3] = {Rl, 0, Rf};
        int Ce[3] = {Cl, 0, Cf};
        int Q[9]  = {c[8], 0, c[7],  0, 0, 0,  c[6], 0, c[5]};
#pragma unroll
        for (int k = 0; k < 9; ++k)
            sT[tid * 9 + k] = (float)(S - Re[k / 3] - Ce[k % 3] + Q[k]);
    }
    __syncthreads();
#pragma unroll 1
    for (int i = 0; i < 16; ++i) {
        const int o = warp * 16 + i;
        const float* wr = w2 + o * 576;
        float acc = 0.f;
#pragma unroll
        for (int t = 0; t < 18; ++t) {
            int j = t * 32 + lane;
            acc = fmaf(__ldg(&wr[j]), sT[j], acc);
        }
#pragma unroll
        for (int s = 16; s; s >>= 1) acc += __shfl_xor_sync(0xffffffffu, acc, s);
        if (lane == 0) {
            float z = acc * (1.f / 16384.f);
            z = z * g_inv2[o] + g_beta2[o];
            g_s2[n][o] = (z > 1.f) ? 1.f : 0.f;
        }
    }
}

// ---------------------------------------------------------------------------
// stage C: feat = |s0 - s1|, fc1+relu, fc2  -> out (32,5)
// grid 32 (n), block 256 (8 warps x 8 k, coalesced fc1w + shfl reduce)
// ---------------------------------------------------------------------------
__global__ __launch_bounds__(256) void stageC_kernel(const float* __restrict__ fc1w,
                                                     const float* __restrict__ fc1b,
                                                     const float* __restrict__ fc2w,
                                                     const float* __restrict__ fc2b,
                                                     float* __restrict__ out) {
    __shared__ float f[128];
    __shared__ float h[64];
    const int n = blockIdx.x, tid = threadIdx.x;
    const int lane = tid & 31, warp = tid >> 5;
    if (tid < 128) f[tid] = fabsf(g_s2[n][tid] - g_s2[n + 32][tid]);
    __syncthreads();
#pragma unroll 1
    for (int i = 0; i < 8; ++i) {
        const int k = warp * 8 + i;
        const float* wr = fc1w + k * 128;
        float acc = 0.f;
#pragma unroll
        for (int t = 0; t < 4; ++t) {
            int j = t * 32 + lane;
            acc = fmaf(__ldg(&wr[j]), f[j], acc);
        }
#pragma unroll
        for (int s = 16; s; s >>= 1) acc += __shfl_xor_sync(0xffffffffu, acc, s);
        if (lane == 0) h[k] = fmaxf(acc + fc1b[k], 0.f);
    }
    __syncthreads();
    if (warp == 0) {
#pragma unroll 1
        for (int c = 0; c < 5; ++c) {
            const float* wr = fc2w + c * 64;
            float acc = fmaf(__ldg(&wr[lane]), h[lane], 0.f);
            acc = fmaf(__ldg(&wr[lane + 32]), h[lane + 32], acc);
#pragma unroll
            for (int s = 16; s; s >>= 1) acc += __shfl_xor_sync(0xffffffffu, acc, s);
            if (lane == 0) out[n * 5 + c] = acc + fc2b[c];
        }
    }
}

extern "C" void kernel_launch(void* const* d_in, const int* in_sizes, int n_in,
                              void* d_out, int out_size) {
    const float* x0   = (const float*)d_in[0];
    const float* x1   = (const float*)d_in[1];
    const float* w1   = (const float*)d_in[2];
    const float* b1g  = (const float*)d_in[3];
    const float* b1b  = (const float*)d_in[4];
    const float* b1m  = (const float*)d_in[5];
    const float* b1v  = (const float*)d_in[6];
    const float* w2   = (const float*)d_in[7];
    const float* b2g  = (const float*)d_in[8];
    const float* b2b  = (const float*)d_in[9];
    const float* b2m  = (const float*)d_in[10];
    const float* b2v  = (const float*)d_in[11];
    const float* fc1w = (const float*)d_in[12];
    const float* fc1b = (const float*)d_in[13];
    const float* fc2w = (const float*)d_in[14];
    const float* fc2b = (const float*)d_in[15];

    prep_kernel<<<32, 256>>>(b1g, b1b, b1m, b1v, b2g, b2b, b2m, b2v);
    dim3 gridA(8, 16, 64);
    stageA_kernel<<<gridA, 128>>>(x0, x1, w1);
    stageB_kernel<<<64, 256>>>(w2);
    stageC_kernel<<<32, 256>>>(fc1w, fc1b, fc2w, fc2b, (float*)d_out);
}